// round 3
// baseline (speedup 1.0000x reference)
#include <cuda_runtime.h>
#include <cstdint>

#define DIMS 2048
#define NCLS 4000
#define NROWS 32768
#define NTHR 256
#define MOM 0.9f
#define EPS 1e-12f

// Scratch: segment sums and counts (graph-safe __device__ globals, no allocs).
// Zero-initialized at module load; finalize re-zeros them after consumption so
// every launch (and every graph replay) starts from a zeroed state.
__device__ float g_seg[2][NCLS][DIMS];   // 65.5 MB — L2-resident working set
__device__ float g_cnt[2][NCLS];

__device__ __forceinline__ float blockReduceSum(float v, float* sh) {
    int lane = threadIdx.x & 31;
    int w = threadIdx.x >> 5;
    #pragma unroll
    for (int o = 16; o > 0; o >>= 1) v += __shfl_xor_sync(0xffffffffu, v, o);
    if (lane == 0) sh[w] = v;
    __syncthreads();
    if (w == 0) {
        float x = (lane < (NTHR >> 5)) ? sh[lane] : 0.f;
        #pragma unroll
        for (int o = 4; o > 0; o >>= 1) x += __shfl_xor_sync(0xffffffffu, x, o);
        if (lane == 0) sh[0] = x;
    }
    __syncthreads();
    float r = sh[0];
    __syncthreads();   // make sh reusable by a following reduction
    return r;
}

__device__ __forceinline__ void red_add_v4(float* addr, float4 v) {
    asm volatile("red.global.add.v4.f32 [%0], {%1,%2,%3,%4};"
                 :: "l"(addr), "f"(v.x), "f"(v.y), "f"(v.z), "f"(v.w)
                 : "memory");
}

// One block per (modality, row). Normalize row, RED-scatter into g_seg[m][id].
__global__ __launch_bounds__(NTHR) void norm_scatter(
    const float* __restrict__ fv, const float* __restrict__ fr,
    const int* __restrict__ idv, const int* __restrict__ idr)
{
    __shared__ float sh[32];
    const int m = blockIdx.y;
    const int row = blockIdx.x;
    const float* f = (m == 0 ? fv : fr) + (size_t)row * DIMS;
    const int id = (m == 0 ? idv : idr)[row];
    const int t = threadIdx.x;

    const float4* f4 = reinterpret_cast<const float4*>(f);
    // Streaming loads: features are read exactly once — evict-first keeps
    // g_seg resident in L2 for the RED traffic.
    float4 a = __ldcs(&f4[t]);
    float4 b = __ldcs(&f4[t + NTHR]);

    float ss = a.x*a.x + a.y*a.y + a.z*a.z + a.w*a.w
             + b.x*b.x + b.y*b.y + b.z*b.z + b.w*b.w;
    ss = blockReduceSum(ss, sh);
    const float scale = 1.f / fmaxf(sqrtf(ss), EPS);

    a.x *= scale; a.y *= scale; a.z *= scale; a.w *= scale;
    b.x *= scale; b.y *= scale; b.z *= scale; b.w *= scale;

    float* dst = &g_seg[m][id][0];
    red_add_v4(dst + 4 * t, a);
    red_add_v4(dst + 4 * (t + NTHR), b);
    if (t == 0) atomicAdd(&g_cnt[m][id], 1.f);
}

// One block per (modality, class): mean -> l2norm -> blend -> l2norm -> select.
// Also re-zeros its g_seg/g_cnt slice for the next launch/replay.
__global__ __launch_bounds__(NTHR) void finalize(
    const float* __restrict__ vism, const float* __restrict__ irm,
    float* __restrict__ out)
{
    __shared__ float sh[32];
    const int m = blockIdx.y;
    const int c = blockIdx.x;
    const int t = threadIdx.x;

    const float* mem = (m == 0 ? vism : irm) + (size_t)c * DIMS;
    const float cnt = g_cnt[m][c];   // all threads read; zeroed only after the
                                     // first blockReduceSum's __syncthreads()

    float4* s4 = reinterpret_cast<float4*>(&g_seg[m][c][0]);
    const float4* m4 = reinterpret_cast<const float4*>(mem);
    float4 s0 = s4[t], s1 = s4[t + NTHR];
    float4 w0 = __ldcs(&m4[t]), w1 = __ldcs(&m4[t + NTHR]);

    // Re-zero scratch slice. Safe: each thread zeroes exactly the elements it
    // already holds in registers (no cross-thread dependence).
    const float4 z = make_float4(0.f, 0.f, 0.f, 0.f);
    s4[t] = z;
    s4[t + NTHR] = z;

    // mean = seg / max(cnt, 1)
    const float invc = 1.f / fmaxf(cnt, 1.f);
    s0.x *= invc; s0.y *= invc; s0.z *= invc; s0.w *= invc;
    s1.x *= invc; s1.y *= invc; s1.z *= invc; s1.w *= invc;

    float ssm = s0.x*s0.x + s0.y*s0.y + s0.z*s0.z + s0.w*s0.w
              + s1.x*s1.x + s1.y*s1.y + s1.z*s1.z + s1.w*s1.w;
    ssm = blockReduceSum(ssm, sh);   // contains __syncthreads(): all cnt reads done
    // NOW it is safe for thread 0 to zero the shared counter.
    if (t == 0) g_cnt[m][c] = 0.f;
    const float inm = 1.f / fmaxf(sqrtf(ssm), EPS);

    // t = MOM*mem + (1-MOM)*mean_n
    float4 t0, t1;
    t0.x = MOM * w0.x + (1.f - MOM) * (s0.x * inm);
    t0.y = MOM * w0.y + (1.f - MOM) * (s0.y * inm);
    t0.z = MOM * w0.z + (1.f - MOM) * (s0.z * inm);
    t0.w = MOM * w0.w + (1.f - MOM) * (s0.w * inm);
    t1.x = MOM * w1.x + (1.f - MOM) * (s1.x * inm);
    t1.y = MOM * w1.y + (1.f - MOM) * (s1.y * inm);
    t1.z = MOM * w1.z + (1.f - MOM) * (s1.z * inm);
    t1.w = MOM * w1.w + (1.f - MOM) * (s1.w * inm);

    float sst = t0.x*t0.x + t0.y*t0.y + t0.z*t0.z + t0.w*t0.w
              + t1.x*t1.x + t1.y*t1.y + t1.z*t1.z + t1.w*t1.w;
    sst = blockReduceSum(sst, sh);
    const float int_ = 1.f / fmaxf(sqrtf(sst), EPS);

    const bool present = (cnt > 0.f);
    float4 o0, o1;
    o0.x = present ? t0.x * int_ : w0.x;
    o0.y = present ? t0.y * int_ : w0.y;
    o0.z = present ? t0.z * int_ : w0.z;
    o0.w = present ? t0.w * int_ : w0.w;
    o1.x = present ? t1.x * int_ : w1.x;
    o1.y = present ? t1.y * int_ : w1.y;
    o1.z = present ? t1.z * int_ : w1.z;
    o1.w = present ? t1.w * int_ : w1.w;

    float4* o4 = reinterpret_cast<float4*>(out + (size_t)m * NCLS * DIMS + (size_t)c * DIMS);
    __stcs(&o4[t], o0);
    __stcs(&o4[t + NTHR], o1);
}

extern "C" void kernel_launch(void* const* d_in, const int* in_sizes, int n_in,
                              void* d_out, int out_size) {
    const float* fv   = (const float*)d_in[0];
    const float* fr   = (const float*)d_in[1];
    const int*   idv  = (const int*)d_in[2];
    const int*   idr  = (const int*)d_in[3];
    const float* vism = (const float*)d_in[4];
    const float* irm  = (const float*)d_in[5];
    float* out = (float*)d_out;

    norm_scatter<<<dim3(NROWS, 2), NTHR>>>(fv, fr, idv, idr);
    finalize<<<dim3(NCLS, 2), NTHR>>>(vism, irm, out);
}

// round 4
// speedup vs baseline: 1.5645x; 1.5645x over previous
#include <cuda_runtime.h>
#include <cstdint>

#define DIMS 2048
#define NCLS 4000
#define NROWS 32768
#define NTHR 256
#define MOM 0.9f
#define EPS 1e-12f

// Graph-safe __device__ scratch (no allocs). All of it is re-initialized
// every launch by the tiny kernels below, so graph replays are clean.
__device__ int g_icnt[2][NCLS];     // per-class row counts
__device__ int g_base[2][NCLS];     // exclusive prefix (bucket start offsets)
__device__ int g_cursor[2][NCLS];   // bucket fill cursors
__device__ int g_rowlist[2][NROWS]; // row indices grouped by class

// ---------------------------------------------------------------- reductions
__device__ __forceinline__ float blockReduceSum(float v, float* sh) {
    int lane = threadIdx.x & 31;
    int w = threadIdx.x >> 5;
    #pragma unroll
    for (int o = 16; o > 0; o >>= 1) v += __shfl_xor_sync(0xffffffffu, v, o);
    if (lane == 0) sh[w] = v;
    __syncthreads();
    if (w == 0) {
        float x = (lane < (NTHR >> 5)) ? sh[lane] : 0.f;
        #pragma unroll
        for (int o = 4; o > 0; o >>= 1) x += __shfl_xor_sync(0xffffffffu, x, o);
        if (lane == 0) sh[0] = x;
    }
    __syncthreads();
    float r = sh[0];
    __syncthreads();
    return r;
}

// Exclusive scan across a 1024-thread block.
__device__ __forceinline__ int blockExclScan(int v, int* sh) {
    int lane = threadIdx.x & 31;
    int w = threadIdx.x >> 5;
    int x = v;
    #pragma unroll
    for (int o = 1; o < 32; o <<= 1) {
        int y = __shfl_up_sync(0xffffffffu, x, o);
        if (lane >= o) x += y;
    }
    if (lane == 31) sh[w] = x;          // warp inclusive totals
    __syncthreads();
    if (w == 0) {
        int s = sh[lane];               // 32 warps exactly
        #pragma unroll
        for (int o = 1; o < 32; o <<= 1) {
            int y = __shfl_up_sync(0xffffffffu, s, o);
            if (lane >= o) s += y;
        }
        sh[lane] = s;                   // inclusive scan of warp totals
    }
    __syncthreads();
    int warpOff = (w == 0) ? 0 : sh[w - 1];
    return warpOff + x - v;
}

// ---------------------------------------------------------------- tiny passes
__global__ void zero_meta() {
    int i = blockIdx.x * blockDim.x + threadIdx.x;
    int* a = &g_icnt[0][0];
    int* b = &g_cursor[0][0];
    if (i < 2 * NCLS) { a[i] = 0; b[i] = 0; }
}

__global__ void hist(const int* __restrict__ idv, const int* __restrict__ idr) {
    int m = blockIdx.y;
    int i = blockIdx.x * blockDim.x + threadIdx.x;
    if (i < NROWS) {
        int id = (m == 0 ? idv : idr)[i];
        atomicAdd(&g_icnt[m][id], 1);
    }
}

__global__ __launch_bounds__(1024) void scan() {
    __shared__ int sh[32];
    const int m = blockIdx.x;
    const int PER = 4;                      // 4096 / 1024
    int base = threadIdx.x * PER;
    int loc[PER];
    int sum = 0;
    #pragma unroll
    for (int i = 0; i < PER; i++) {
        int v = (base + i < NCLS) ? g_icnt[m][base + i] : 0;
        loc[i] = sum;
        sum += v;
    }
    int excl = blockExclScan(sum, sh);
    #pragma unroll
    for (int i = 0; i < PER; i++)
        if (base + i < NCLS) g_base[m][base + i] = excl + loc[i];
}

__global__ void bucket(const int* __restrict__ idv, const int* __restrict__ idr) {
    int m = blockIdx.y;
    int i = blockIdx.x * blockDim.x + threadIdx.x;
    if (i < NROWS) {
        int id = (m == 0 ? idv : idr)[i];
        int pos = g_base[m][id] + atomicAdd(&g_cursor[m][id], 1);
        g_rowlist[m][pos] = i;
    }
}

// ------------------------------------------------- fused gather + finalize
// One block per (class, modality). Gathers the class's rows, normalizes each
// in-block, accumulates the segment sum in registers, then does
// mean -> l2norm -> blend -> l2norm -> select and writes the output row.
__global__ __launch_bounds__(NTHR) void gather_finalize(
    const float* __restrict__ fv, const float* __restrict__ fr,
    const float* __restrict__ vism, const float* __restrict__ irm,
    float* __restrict__ out)
{
    __shared__ float sh[32];
    const int m = blockIdx.y;
    const int c = blockIdx.x;
    const int t = threadIdx.x;

    const float* feat = (m == 0 ? fv : fr);
    const int start = g_base[m][c];
    const int cnt   = g_icnt[m][c];

    // Kick off the memory-row load early; it's consumed at the very end.
    const float4* m4 = reinterpret_cast<const float4*>(
        (m == 0 ? vism : irm) + (size_t)c * DIMS);
    float4 w0 = __ldcs(&m4[t]), w1 = __ldcs(&m4[t + NTHR]);

    float4 acc0 = make_float4(0.f, 0.f, 0.f, 0.f);
    float4 acc1 = make_float4(0.f, 0.f, 0.f, 0.f);

    // Software pipeline: prefetch row r+1 before reducing row r.
    float4 a, b;
    if (cnt > 0) {
        const float4* f4 = reinterpret_cast<const float4*>(
            feat + (size_t)g_rowlist[m][start] * DIMS);
        a = __ldcs(&f4[t]);
        b = __ldcs(&f4[t + NTHR]);
    }
    for (int r = 0; r < cnt; ++r) {
        float4 na, nb;
        if (r + 1 < cnt) {
            const float4* f4 = reinterpret_cast<const float4*>(
                feat + (size_t)g_rowlist[m][start + r + 1] * DIMS);
            na = __ldcs(&f4[t]);
            nb = __ldcs(&f4[t + NTHR]);
        }
        float ss = a.x*a.x + a.y*a.y + a.z*a.z + a.w*a.w
                 + b.x*b.x + b.y*b.y + b.z*b.z + b.w*b.w;
        ss = blockReduceSum(ss, sh);
        const float sc = 1.f / fmaxf(sqrtf(ss), EPS);
        acc0.x += sc * a.x; acc0.y += sc * a.y; acc0.z += sc * a.z; acc0.w += sc * a.w;
        acc1.x += sc * b.x; acc1.y += sc * b.y; acc1.z += sc * b.z; acc1.w += sc * b.w;
        if (r + 1 < cnt) { a = na; b = nb; }
    }

    // mean = acc / max(cnt, 1)
    const float invc = 1.f / fmaxf((float)cnt, 1.f);
    acc0.x *= invc; acc0.y *= invc; acc0.z *= invc; acc0.w *= invc;
    acc1.x *= invc; acc1.y *= invc; acc1.z *= invc; acc1.w *= invc;

    float ssm = acc0.x*acc0.x + acc0.y*acc0.y + acc0.z*acc0.z + acc0.w*acc0.w
              + acc1.x*acc1.x + acc1.y*acc1.y + acc1.z*acc1.z + acc1.w*acc1.w;
    ssm = blockReduceSum(ssm, sh);
    const float inm = 1.f / fmaxf(sqrtf(ssm), EPS);

    float4 t0, t1;
    t0.x = MOM * w0.x + (1.f - MOM) * (acc0.x * inm);
    t0.y = MOM * w0.y + (1.f - MOM) * (acc0.y * inm);
    t0.z = MOM * w0.z + (1.f - MOM) * (acc0.z * inm);
    t0.w = MOM * w0.w + (1.f - MOM) * (acc0.w * inm);
    t1.x = MOM * w1.x + (1.f - MOM) * (acc1.x * inm);
    t1.y = MOM * w1.y + (1.f - MOM) * (acc1.y * inm);
    t1.z = MOM * w1.z + (1.f - MOM) * (acc1.z * inm);
    t1.w = MOM * w1.w + (1.f - MOM) * (acc1.w * inm);

    float sst = t0.x*t0.x + t0.y*t0.y + t0.z*t0.z + t0.w*t0.w
              + t1.x*t1.x + t1.y*t1.y + t1.z*t1.z + t1.w*t1.w;
    sst = blockReduceSum(sst, sh);
    const float int_ = 1.f / fmaxf(sqrtf(sst), EPS);

    const bool present = (cnt > 0);
    float4 o0, o1;
    o0.x = present ? t0.x * int_ : w0.x;
    o0.y = present ? t0.y * int_ : w0.y;
    o0.z = present ? t0.z * int_ : w0.z;
    o0.w = present ? t0.w * int_ : w0.w;
    o1.x = present ? t1.x * int_ : w1.x;
    o1.y = present ? t1.y * int_ : w1.y;
    o1.z = present ? t1.z * int_ : w1.z;
    o1.w = present ? t1.w * int_ : w1.w;

    float4* o4 = reinterpret_cast<float4*>(out + (size_t)m * NCLS * DIMS + (size_t)c * DIMS);
    __stcs(&o4[t], o0);
    __stcs(&o4[t + NTHR], o1);
}

extern "C" void kernel_launch(void* const* d_in, const int* in_sizes, int n_in,
                              void* d_out, int out_size) {
    const float* fv   = (const float*)d_in[0];
    const float* fr   = (const float*)d_in[1];
    const int*   idv  = (const int*)d_in[2];
    const int*   idr  = (const int*)d_in[3];
    const float* vism = (const float*)d_in[4];
    const float* irm  = (const float*)d_in[5];
    float* out = (float*)d_out;

    zero_meta<<<(2 * NCLS + 255) / 256, 256>>>();
    hist<<<dim3((NROWS + 255) / 256, 2), 256>>>(idv, idr);
    scan<<<2, 1024>>>();
    bucket<<<dim3((NROWS + 255) / 256, 2), 256>>>(idv, idr);
    gather_finalize<<<dim3(NCLS, 2), NTHR>>>(fv, fr, vism, irm, out);
}